// round 3
// baseline (speedup 1.0000x reference)
#include <cuda_runtime.h>
#include <math.h>

#define NN   10000
#define EE   160000
#define FIN  2208
#define HH   512
#define CC   2
#define NNZ  (EE + NN)

// ---------------- scratch (static device globals; no allocation) ----------------
__device__ float g_bufA[NN * HH];   // GEMM output
__device__ float g_bufB[NN * HH];   // aggregation output
__device__ float g_t[NN * CC];      // layer-4 pre-aggregation logits
__device__ int   g_degi[NN];
__device__ float g_dinv[NN];
__device__ int   g_rowptr[NN + 1];
__device__ int   g_cursor[NN];
__device__ int   g_colsrc[NNZ];
__device__ float g_w[NNZ];

// ---------------- graph preprocessing ----------------

__global__ void init_deg_kernel() {
    int i = blockIdx.x * blockDim.x + threadIdx.x;
    if (i < NN) g_degi[i] = 1;   // self loop
}

__global__ void count_deg_kernel(const int* __restrict__ ei) {
    int e = blockIdx.x * blockDim.x + threadIdx.x;
    if (e < EE) {
        int d = ei[EE + e];
        atomicAdd(&g_degi[d], 1);
    }
}

// single-block exclusive scan of deg -> rowptr, also dinv and cursor init
__global__ void scan_kernel() {
    __shared__ int sh[1024];
    __shared__ int carry_sh;
    int tid = threadIdx.x;
    if (tid == 0) carry_sh = 0;
    __syncthreads();
    for (int base = 0; base < NN; base += 1024) {
        int i = base + tid;
        int v = (i < NN) ? g_degi[i] : 0;
        sh[tid] = v;
        __syncthreads();
        for (int off = 1; off < 1024; off <<= 1) {
            int t = (tid >= off) ? sh[tid - off] : 0;
            __syncthreads();
            sh[tid] += t;
            __syncthreads();
        }
        int incl = sh[tid];
        int excl = incl - v;
        int c = carry_sh;
        if (i < NN) {
            g_rowptr[i] = c + excl;
            g_cursor[i] = c + excl;
            g_dinv[i]   = rsqrtf((float)v);
        }
        __syncthreads();
        if (tid == 0) carry_sh = c + sh[1023];
        __syncthreads();
    }
    if (tid == 0) g_rowptr[NN] = carry_sh;   // == NNZ
}

__global__ void fill_csr_kernel(const int* __restrict__ ei) {
    int e = blockIdx.x * blockDim.x + threadIdx.x;
    if (e < EE) {
        int s = ei[e];
        int d = ei[EE + e];
        int slot = atomicAdd(&g_cursor[d], 1);
        g_colsrc[slot] = s;
        g_w[slot] = g_dinv[s] * g_dinv[d];
    } else if (e < EE + NN) {
        int i = e - EE;
        int slot = atomicAdd(&g_cursor[i], 1);
        g_colsrc[slot] = i;
        g_w[slot] = g_dinv[i] * g_dinv[i];
    }
}

// ---------------- SGEMM: C[M,N] = A[M,K] @ B[K,N], row-major, fp32 ----------------
// 128x128 tile, BK=8, 256 threads, 8x8 per thread.
__global__ __launch_bounds__(256) void sgemm_kernel(
    const float* __restrict__ A, const float* __restrict__ B,
    float* __restrict__ C, int M, int N, int K)
{
    const int BM = 128, BN = 128, BK = 8, TM = 8, TN = 8;
    __shared__ float As[BK][BM];
    __shared__ float Bs[BK][BN];

    int tid = threadIdx.x;
    int tx = tid & 15;       // 0..15 (N dir)
    int ty = tid >> 4;       // 0..15 (M dir)
    int rowBase = blockIdx.y * BM;
    int colBase = blockIdx.x * BN;

    float acc[TM][TN];
#pragma unroll
    for (int i = 0; i < TM; i++)
#pragma unroll
        for (int j = 0; j < TN; j++) acc[i][j] = 0.f;

    // A tile loader mapping: 128 rows x 8 cols = 1024 floats -> 256 threads x float4
    int arow = tid >> 1;           // 0..127
    int acol = (tid & 1) * 4;      // 0 or 4
    // B tile loader: 8 rows x 128 cols -> 256 threads x float4
    int brow = tid >> 5;           // 0..7
    int bcol = (tid & 31) * 4;     // 0..124

    for (int k0 = 0; k0 < K; k0 += BK) {
        float4 av = make_float4(0.f, 0.f, 0.f, 0.f);
        int gr = rowBase + arow;
        if (gr < M)
            av = *(const float4*)&A[(size_t)gr * K + k0 + acol];
        As[acol + 0][arow] = av.x;
        As[acol + 1][arow] = av.y;
        As[acol + 2][arow] = av.z;
        As[acol + 3][arow] = av.w;

        float4 bv = *(const float4*)&B[(size_t)(k0 + brow) * N + colBase + bcol];
        *(float4*)&Bs[brow][bcol] = bv;
        __syncthreads();

#pragma unroll
        for (int kk = 0; kk < BK; kk++) {
            float ar[TM], br[TN];
            float4 a0 = *(const float4*)&As[kk][ty * TM + 0];
            float4 a1 = *(const float4*)&As[kk][ty * TM + 4];
            ar[0]=a0.x; ar[1]=a0.y; ar[2]=a0.z; ar[3]=a0.w;
            ar[4]=a1.x; ar[5]=a1.y; ar[6]=a1.z; ar[7]=a1.w;
            float4 b0 = *(const float4*)&Bs[kk][tx * TN + 0];
            float4 b1 = *(const float4*)&Bs[kk][tx * TN + 4];
            br[0]=b0.x; br[1]=b0.y; br[2]=b0.z; br[3]=b0.w;
            br[4]=b1.x; br[5]=b1.y; br[6]=b1.z; br[7]=b1.w;
#pragma unroll
            for (int i = 0; i < TM; i++)
#pragma unroll
                for (int j = 0; j < TN; j++)
                    acc[i][j] += ar[i] * br[j];
        }
        __syncthreads();
    }

#pragma unroll
    for (int i = 0; i < TM; i++) {
        int r = rowBase + ty * TM + i;
        if (r >= M) continue;
#pragma unroll
        for (int j = 0; j < TN; j += 4) {
            float4 v = make_float4(acc[i][j], acc[i][j+1], acc[i][j+2], acc[i][j+3]);
            *(float4*)&C[(size_t)r * N + colBase + tx * TN + j] = v;
        }
    }
}

// ---------------- aggregation: out[i,:] = relu?( sum_e w*in[col,:] + b ) ----------
// one warp per node, 512 features, lane handles 4 interleaved float4s
__global__ __launch_bounds__(256) void aggregate512_kernel(
    const float* __restrict__ in, float* __restrict__ out,
    const float* __restrict__ bias, int do_relu)
{
    int gw = (blockIdx.x * blockDim.x + threadIdx.x) >> 5;
    int lane = threadIdx.x & 31;
    if (gw >= NN) return;
    int beg = g_rowptr[gw], end = g_rowptr[gw + 1];

    float4 acc[4];
#pragma unroll
    for (int j = 0; j < 4; j++) acc[j] = make_float4(0.f, 0.f, 0.f, 0.f);

    for (int e = beg; e < end; e++) {
        int c = g_colsrc[e];
        float w = g_w[e];
        const float4* row = (const float4*)(in + (size_t)c * HH);
#pragma unroll
        for (int j = 0; j < 4; j++) {
            float4 v = row[j * 32 + lane];
            acc[j].x += w * v.x;
            acc[j].y += w * v.y;
            acc[j].z += w * v.z;
            acc[j].w += w * v.w;
        }
    }
#pragma unroll
    for (int j = 0; j < 4; j++) {
        int f = (j * 32 + lane) * 4;
        float4 bv = *(const float4*)&bias[f];
        float4 r;
        r.x = acc[j].x + bv.x;
        r.y = acc[j].y + bv.y;
        r.z = acc[j].z + bv.z;
        r.w = acc[j].w + bv.w;
        if (do_relu) {
            r.x = fmaxf(r.x, 0.f); r.y = fmaxf(r.y, 0.f);
            r.z = fmaxf(r.z, 0.f); r.w = fmaxf(r.w, 0.f);
        }
        *(float4*)&out[(size_t)gw * HH + f] = r;
    }
}

// ---------------- layer 4: t = h3 @ W4   (512 -> 2), warp per node --------------
__global__ __launch_bounds__(256) void gemm_small_kernel(
    const float* __restrict__ h, const float* __restrict__ W4, float* __restrict__ t)
{
    __shared__ float w[HH * CC];
    int tid = threadIdx.x;
    for (int i = tid; i < HH * CC; i += blockDim.x) w[i] = W4[i];
    __syncthreads();
    int gw = (blockIdx.x * blockDim.x + tid) >> 5;
    int lane = tid & 31;
    if (gw >= NN) return;
    float a0 = 0.f, a1 = 0.f;
    const float* hr = h + (size_t)gw * HH;
    for (int k = lane; k < HH; k += 32) {
        float hv = hr[k];
        a0 += hv * w[2 * k + 0];
        a1 += hv * w[2 * k + 1];
    }
#pragma unroll
    for (int off = 16; off > 0; off >>= 1) {
        a0 += __shfl_down_sync(0xFFFFFFFFu, a0, off);
        a1 += __shfl_down_sync(0xFFFFFFFFu, a1, off);
    }
    if (lane == 0) {
        t[gw * 2 + 0] = a0;
        t[gw * 2 + 1] = a1;
    }
}

// ---------------- final: aggregate 2-wide + bias + log_softmax ------------------
__global__ void finalize_kernel(const float* __restrict__ t,
                                const float* __restrict__ b4,
                                float* __restrict__ out)
{
    int i = blockIdx.x * blockDim.x + threadIdx.x;
    if (i >= NN) return;
    float z0 = 0.f, z1 = 0.f;
    int beg = g_rowptr[i], end = g_rowptr[i + 1];
    for (int e = beg; e < end; e++) {
        int c = g_colsrc[e];
        float w = g_w[e];
        z0 += w * t[2 * c + 0];
        z1 += w * t[2 * c + 1];
    }
    z0 += b4[0];
    z1 += b4[1];
    float m = fmaxf(z0, z1);
    float lse = m + logf(expf(z0 - m) + expf(z1 - m));
    out[2 * i + 0] = z0 - lse;
    out[2 * i + 1] = z1 - lse;
}

// ---------------- launch ----------------
extern "C" void kernel_launch(void* const* d_in, const int* in_sizes, int n_in,
                              void* d_out, int out_size)
{
    const float* x  = (const float*)d_in[0];
    const int*   ei = (const int*)d_in[1];   // int32: JAX x64 disabled downcasts int64
    // d_in[2] = batch (unused, single graph)
    const float* W1 = (const float*)d_in[3];
    const float* b1 = (const float*)d_in[4];
    const float* W2 = (const float*)d_in[5];
    const float* b2 = (const float*)d_in[6];
    const float* W3 = (const float*)d_in[7];
    const float* b3 = (const float*)d_in[8];
    const float* W4 = (const float*)d_in[9];
    const float* b4 = (const float*)d_in[10];
    float* out = (float*)d_out;

    float *pA, *pB, *pT;
    cudaGetSymbolAddress((void**)&pA, g_bufA);
    cudaGetSymbolAddress((void**)&pB, g_bufB);
    cudaGetSymbolAddress((void**)&pT, g_t);

    // graph preprocessing (CSR by destination, incl. self loops + sym norm)
    init_deg_kernel<<<(NN + 255) / 256, 256>>>();
    count_deg_kernel<<<(EE + 255) / 256, 256>>>(ei);
    scan_kernel<<<1, 1024>>>();
    fill_csr_kernel<<<(NNZ + 255) / 256, 256>>>(ei);

    dim3 gemm_grid(HH / 128, (NN + 127) / 128);   // (4, 79)
    int agg_blocks = (NN * 32 + 255) / 256;       // 1250

    // layer 1
    sgemm_kernel<<<gemm_grid, 256>>>(x, W1, pA, NN, HH, FIN);
    aggregate512_kernel<<<agg_blocks, 256>>>(pA, pB, b1, 1);
    // layer 2
    sgemm_kernel<<<gemm_grid, 256>>>(pB, W2, pA, NN, HH, HH);
    aggregate512_kernel<<<agg_blocks, 256>>>(pA, pB, b2, 1);
    // layer 3
    sgemm_kernel<<<gemm_grid, 256>>>(pB, W3, pA, NN, HH, HH);
    aggregate512_kernel<<<agg_blocks, 256>>>(pA, pB, b3, 1);
    // layer 4 + log_softmax
    gemm_small_kernel<<<agg_blocks, 256>>>(pB, W4, pT);
    finalize_kernel<<<(NN + 255) / 256, 256>>>(pT, b4, out);
}

// round 7
// speedup vs baseline: 2.7852x; 2.7852x over previous
#include <cuda_runtime.h>
#include <cuda_bf16.h>
#include <math.h>
#include <stdint.h>

#define NN   10000
#define EE   160000
#define FIN  2208
#define KP1  2240          // FIN padded to multiple of 32
#define HH   512
#define CC   2
#define NNZ  (EE + NN)

// ---------------- scratch (static device globals; no allocation) ----------------
__device__ float g_bufA[NN * HH];            // GEMM output
__device__ float g_bufB[NN * HH];            // aggregation fp32 output (layer 3)
__device__ float g_t[NN * CC];
__device__ int   g_degi[NN];
__device__ float g_dinv[NN];
__device__ int   g_rowptr[NN + 1];
__device__ int   g_cursor[NN];
__device__ int   g_colsrc[NNZ];
__device__ float g_w[NNZ];
__device__ __align__(16) __nv_bfloat16 g_Ahi[NN * KP1];
__device__ __align__(16) __nv_bfloat16 g_Alo[NN * KP1];
__device__ __align__(16) __nv_bfloat16 g_Bhi[HH * KP1];
__device__ __align__(16) __nv_bfloat16 g_Blo[HH * KP1];

// ---------------- PTX helpers (sm_80-baseline, compile at compute_103) ----------
__device__ __forceinline__ uint32_t smem_u32(const void* p) {
    uint32_t a;
    asm("{ .reg .u64 t; cvta.to.shared.u64 t, %1; cvt.u32.u64 %0, t; }" : "=r"(a) : "l"(p));
    return a;
}
__device__ __forceinline__ void cpa16(uint32_t s, const void* g, int sz) {
    asm volatile("cp.async.cg.shared.global [%0], [%1], 16, %2;"
                 :: "r"(s), "l"(g), "r"(sz) : "memory");
}
__device__ __forceinline__ void cpa_commit() {
    asm volatile("cp.async.commit_group;" ::: "memory");
}
template <int N> __device__ __forceinline__ void cpa_wait() {
    asm volatile("cp.async.wait_group %0;" :: "n"(N) : "memory");
}
__device__ __forceinline__ void ldsm4(uint32_t& r0, uint32_t& r1, uint32_t& r2, uint32_t& r3,
                                      uint32_t addr) {
    asm volatile("ldmatrix.sync.aligned.m8n8.x4.shared.b16 {%0,%1,%2,%3}, [%4];"
                 : "=r"(r0), "=r"(r1), "=r"(r2), "=r"(r3) : "r"(addr));
}
__device__ __forceinline__ void mma16816(float* d, const uint32_t* a, const uint32_t* b) {
    asm volatile(
        "mma.sync.aligned.m16n8k16.row.col.f32.bf16.bf16.f32 "
        "{%0,%1,%2,%3}, {%4,%5,%6,%7}, {%8,%9}, {%0,%1,%2,%3};"
        : "+f"(d[0]), "+f"(d[1]), "+f"(d[2]), "+f"(d[3])
        : "r"(a[0]), "r"(a[1]), "r"(a[2]), "r"(a[3]), "r"(b[0]), "r"(b[1]));
}

// ---------------- graph preprocessing ----------------
__global__ void init_deg_kernel() {
    int i = blockIdx.x * blockDim.x + threadIdx.x;
    if (i < NN) g_degi[i] = 1;
}
__global__ void count_deg_kernel(const int* __restrict__ ei) {
    int e = blockIdx.x * blockDim.x + threadIdx.x;
    if (e < EE) atomicAdd(&g_degi[ei[EE + e]], 1);
}
__global__ void scan_kernel() {
    __shared__ int sh[1024];
    __shared__ int carry_sh;
    int tid = threadIdx.x;
    if (tid == 0) carry_sh = 0;
    __syncthreads();
    for (int base = 0; base < NN; base += 1024) {
        int i = base + tid;
        int v = (i < NN) ? g_degi[i] : 0;
        sh[tid] = v;
        __syncthreads();
        for (int off = 1; off < 1024; off <<= 1) {
            int t = (tid >= off) ? sh[tid - off] : 0;
            __syncthreads();
            sh[tid] += t;
            __syncthreads();
        }
        int excl = sh[tid] - v;
        int c = carry_sh;
        if (i < NN) {
            g_rowptr[i] = c + excl;
            g_cursor[i] = c + excl;
            g_dinv[i]   = rsqrtf((float)v);
        }
        __syncthreads();
        if (tid == 0) carry_sh = c + sh[1023];
        __syncthreads();
    }
    if (tid == 0) g_rowptr[NN] = carry_sh;
}
__global__ void fill_csr_kernel(const int* __restrict__ ei) {
    int e = blockIdx.x * blockDim.x + threadIdx.x;
    if (e < EE) {
        int s = ei[e], d = ei[EE + e];
        int slot = atomicAdd(&g_cursor[d], 1);
        g_colsrc[slot] = s;
        g_w[slot] = g_dinv[s] * g_dinv[d];
    } else if (e < EE + NN) {
        int i = e - EE;
        int slot = atomicAdd(&g_cursor[i], 1);
        g_colsrc[slot] = i;
        g_w[slot] = g_dinv[i] * g_dinv[i];
    }
}

// ---------------- split-precision conversion ----------------
__global__ void convA_kernel(const float* __restrict__ src, int Kin, int Kpad) {
    int k = blockIdx.x * blockDim.x + threadIdx.x;
    int m = blockIdx.y;
    if (k >= Kpad) return;
    float v = (k < Kin) ? src[(size_t)m * Kin + k] : 0.f;
    __nv_bfloat16 h = __float2bfloat16(v);
    g_Ahi[(size_t)m * Kpad + k] = h;
    g_Alo[(size_t)m * Kpad + k] = __float2bfloat16(v - __bfloat162float(h));
}
// W: fp32 [Kin, 512] -> transposed hi/lo bf16 [512][Kpad]
__global__ void convB_kernel(const float* __restrict__ W, int Kin, int Kpad) {
    int k = blockIdx.x * blockDim.x + threadIdx.x;
    int n = blockIdx.y;
    if (k >= Kpad) return;
    float v = (k < Kin) ? W[(size_t)k * HH + n] : 0.f;
    __nv_bfloat16 h = __float2bfloat16(v);
    g_Bhi[(size_t)n * Kpad + k] = h;
    g_Blo[(size_t)n * Kpad + k] = __float2bfloat16(v - __bfloat162float(h));
}

// ---------------- MMA GEMM: C[M,512] = A @ B^T (3-term split bf16, fp32 acc) -----
// BM=128, BN=64, BK=32; 256 threads = 8 warps (4Mx2N), warp tile 32x32.
// smem per stage: Ahi 8K | Alo 8K | Bhi 4K | Blo 4K = 24K; double buffered = 48K.
#define STG 24576
#define OFF_ALO 8192
#define OFF_BHI 16384
#define OFF_BLO 20480
// swizzled byte offset for (row, 16B-seg) in a 64B-pitch tile
#define SWZ(r, s) (((r) << 6) + ((((s) ^ (((r) >> 1) & 3))) << 4))

__device__ __forceinline__ void issue_chunk(
    uint32_t sb, int stage, int k0, int tid, int rowBase, int colBase, int M, int Kpad,
    const __nv_bfloat16* Ahi, const __nv_bfloat16* Alo,
    const __nv_bfloat16* Bhi, const __nv_bfloat16* Blo)
{
    uint32_t st = sb + stage * STG;
#pragma unroll
    for (int s = 0; s < 2; s++) {                 // A: 512 segs, 2/thread
        int idx = tid + s * 256;
        int r = idx >> 2, kseg = idx & 3;
        int grow = rowBase + r;
        int valid = (grow < M);
        size_t goff = (size_t)(valid ? grow : 0) * Kpad + k0 + kseg * 8;
        uint32_t soff = SWZ(r, kseg);
        int sz = valid ? 16 : 0;
        cpa16(st + soff,           Ahi + goff, sz);
        cpa16(st + OFF_ALO + soff, Alo + goff, sz);
    }
    {                                             // B: 256 segs, 1/thread
        int r = tid >> 2, kseg = tid & 3;
        size_t goff = (size_t)(colBase + r) * Kpad + k0 + kseg * 8;
        uint32_t soff = SWZ(r, kseg);
        cpa16(st + OFF_BHI + soff, Bhi + goff, 16);
        cpa16(st + OFF_BLO + soff, Blo + goff, 16);
    }
}

__global__ __launch_bounds__(256) void mma_gemm_kernel(
    const __nv_bfloat16* __restrict__ Ahi, const __nv_bfloat16* __restrict__ Alo,
    const __nv_bfloat16* __restrict__ Bhi, const __nv_bfloat16* __restrict__ Blo,
    float* __restrict__ C, int M, int Kpad)
{
    extern __shared__ char smem[];
    uint32_t sb = smem_u32(smem);
    int tid = threadIdx.x, lane = tid & 31, wid = tid >> 5;
    int wm = wid >> 1, wn = wid & 1;
    int rowBase = blockIdx.y * 128, colBase = blockIdx.x * 64;
    int NC = Kpad >> 5;

    float d[2][4][4];
#pragma unroll
    for (int i = 0; i < 2; i++)
#pragma unroll
        for (int j = 0; j < 4; j++)
#pragma unroll
            for (int k = 0; k < 4; k++) d[i][j][k] = 0.f;

    issue_chunk(sb, 0, 0, tid, rowBase, colBase, M, Kpad, Ahi, Alo, Bhi, Blo);
    cpa_commit();

    // per-lane ldmatrix address components (row/seg within tile)
    int a_r = (lane & 7) + (((lane >> 3) & 1) << 3);   // + mt*16 + wm*32
    int a_s = lane >> 4;                               // + ks*2
    int b_r = (lane & 7) + ((lane >> 4) << 3);         // + half*16 + wn*32
    int b_s = (lane >> 3) & 1;                         // + ks*2

    for (int i = 0; i < NC; i++) {
        if (i + 1 < NC) {
            issue_chunk(sb, (i + 1) & 1, (i + 1) << 5, tid, rowBase, colBase, M, Kpad,
                        Ahi, Alo, Bhi, Blo);
            cpa_commit();
            cpa_wait<1>();
        } else {
            cpa_wait<0>();
        }
        __syncthreads();
        uint32_t st = sb + (i & 1) * STG;
#pragma unroll
        for (int ks = 0; ks < 2; ks++) {
            uint32_t ah[2][4], al[2][4], bh[4][2], bl[4][2];
#pragma unroll
            for (int mt = 0; mt < 2; mt++) {
                int row = wm * 32 + mt * 16 + a_r;
                uint32_t off = SWZ(row, ks * 2 + a_s);
                ldsm4(ah[mt][0], ah[mt][1], ah[mt][2], ah[mt][3], st + off);
                ldsm4(al[mt][0], al[mt][1], al[mt][2], al[mt][3], st + OFF_ALO + off);
            }
#pragma unroll
            for (int h = 0; h < 2; h++) {
                int n = wn * 32 + h * 16 + b_r;
                uint32_t off = SWZ(n, ks * 2 + b_s);
                uint32_t r0, r1, r2, r3;
                ldsm4(r0, r1, r2, r3, st + OFF_BHI + off);
                bh[h * 2][0] = r0; bh[h * 2][1] = r1;
                bh[h * 2 + 1][0] = r2; bh[h * 2 + 1][1] = r3;
                ldsm4(r0, r1, r2, r3, st + OFF_BLO + off);
                bl[h * 2][0] = r0; bl[h * 2][1] = r1;
                bl[h * 2 + 1][0] = r2; bl[h * 2 + 1][1] = r3;
            }
#pragma unroll
            for (int mt = 0; mt < 2; mt++)
#pragma unroll
                for (int nt = 0; nt < 4; nt++) {
                    mma16816(d[mt][nt], ah[mt], bh[nt]);
                    mma16816(d[mt][nt], ah[mt], bl[nt]);
                    mma16816(d[mt][nt], al[mt], bh[nt]);
                }
        }
        __syncthreads();
    }

    // epilogue
#pragma unroll
    for (int mt = 0; mt < 2; mt++)
#pragma unroll
        for (int nt = 0; nt < 4; nt++) {
            int rg = rowBase + wm * 32 + mt * 16 + (lane >> 2);
            int cg = colBase + wn * 32 + nt * 8 + (lane & 3) * 2;
            if (rg < M)
                *(float2*)&C[(size_t)rg * HH + cg] = make_float2(d[mt][nt][0], d[mt][nt][1]);
            if (rg + 8 < M)
                *(float2*)&C[(size_t)(rg + 8) * HH + cg] = make_float2(d[mt][nt][2], d[mt][nt][3]);
        }
}

// ---------------- aggregation (+bias, +relu), fused hi/lo split output -----------
// mode 0: write fp32 to outf; mode 1: write bf16 hi/lo (pitch 512) to g_Ahi/g_Alo
__global__ __launch_bounds__(256) void aggregate512_kernel(
    const float* __restrict__ in, float* __restrict__ outf,
    const float* __restrict__ bias, int do_relu, int mode)
{
    int gw = (blockIdx.x * blockDim.x + threadIdx.x) >> 5;
    int lane = threadIdx.x & 31;
    if (gw >= NN) return;
    int beg = g_rowptr[gw], end = g_rowptr[gw + 1];

    float4 acc[4];
#pragma unroll
    for (int j = 0; j < 4; j++) acc[j] = make_float4(0.f, 0.f, 0.f, 0.f);

    for (int e = beg; e < end; e++) {
        int c = g_colsrc[e];
        float w = g_w[e];
        const float4* row = (const float4*)(in + (size_t)c * HH);
#pragma unroll
        for (int j = 0; j < 4; j++) {
            float4 v = row[j * 32 + lane];
            acc[j].x += w * v.x; acc[j].y += w * v.y;
            acc[j].z += w * v.z; acc[j].w += w * v.w;
        }
    }
#pragma unroll
    for (int j = 0; j < 4; j++) {
        int f = (j * 32 + lane) * 4;
        float4 bv = *(const float4*)&bias[f];
        float4 r;
        r.x = acc[j].x + bv.x; r.y = acc[j].y + bv.y;
        r.z = acc[j].z + bv.z; r.w = acc[j].w + bv.w;
        if (do_relu) {
            r.x = fmaxf(r.x, 0.f); r.y = fmaxf(r.y, 0.f);
            r.z = fmaxf(r.z, 0.f); r.w = fmaxf(r.w, 0.f);
        }
        if (mode == 0) {
            *(float4*)&outf[(size_t)gw * HH + f] = r;
        } else {
            __nv_bfloat16 hx = __float2bfloat16(r.x), hy = __float2bfloat16(r.y);
            __nv_bfloat16 hz = __float2bfloat16(r.z), hw = __float2bfloat16(r.w);
            __nv_bfloat162 h01 = __nv_bfloat162(hx, hy), h23 = __nv_bfloat162(hz, hw);
            __nv_bfloat162 l01 = __nv_bfloat162(
                __float2bfloat16(r.x - __bfloat162float(hx)),
                __float2bfloat16(r.y - __bfloat162float(hy)));
            __nv_bfloat162 l23 = __nv_bfloat162(
                __float2bfloat16(r.z - __bfloat162float(hz)),
                __float2bfloat16(r.w - __bfloat162float(hw)));
            *(__nv_bfloat162*)&g_Ahi[(size_t)gw * HH + f]     = h01;
            *(__nv_bfloat162*)&g_Ahi[(size_t)gw * HH + f + 2] = h23;
            *(__nv_bfloat162*)&g_Alo[(size_t)gw * HH + f]     = l01;
            *(__nv_bfloat162*)&g_Alo[(size_t)gw * HH + f + 2] = l23;
        }
    }
}

// ---------------- layer 4 + finalize ----------------
__global__ __launch_bounds__(256) void gemm_small_kernel(
    const float* __restrict__ h, const float* __restrict__ W4, float* __restrict__ t)
{
    __shared__ float w[HH * CC];
    int tid = threadIdx.x;
    for (int i = tid; i < HH * CC; i += blockDim.x) w[i] = W4[i];
    __syncthreads();
    int gw = (blockIdx.x * blockDim.x + tid) >> 5;
    int lane = tid & 31;
    if (gw >= NN) return;
    float a0 = 0.f, a1 = 0.f;
    const float* hr = h + (size_t)gw * HH;
    for (int k = lane; k < HH; k += 32) {
        float hv = hr[k];
        a0 += hv * w[2 * k + 0];
        a1 += hv * w[2 * k + 1];
    }
#pragma unroll
    for (int off = 16; off > 0; off >>= 1) {
        a0 += __shfl_down_sync(0xFFFFFFFFu, a0, off);
        a1 += __shfl_down_sync(0xFFFFFFFFu, a1, off);
    }
    if (lane == 0) { t[gw * 2 + 0] = a0; t[gw * 2 + 1] = a1; }
}

__global__ void finalize_kernel(const float* __restrict__ t,
                                const float* __restrict__ b4,
                                float* __restrict__ out)
{
    int i = blockIdx.x * blockDim.x + threadIdx.x;
    if (i >= NN) return;
    float z0 = 0.f, z1 = 0.f;
    int beg = g_rowptr[i], end = g_rowptr[i + 1];
    for (int e = beg; e < end; e++) {
        int c = g_colsrc[e];
        float w = g_w[e];
        z0 += w * t[2 * c + 0];
        z1 += w * t[2 * c + 1];
    }
    z0 += b4[0]; z1 += b4[1];
    float m = fmaxf(z0, z1);
    float lse = m + logf(expf(z0 - m) + expf(z1 - m));
    out[2 * i + 0] = z0 - lse;
    out[2 * i + 1] = z1 - lse;
}

// ---------------- launch ----------------
extern "C" void kernel_launch(void* const* d_in, const int* in_sizes, int n_in,
                              void* d_out, int out_size)
{
    const float* x  = (const float*)d_in[0];
    const int*   ei = (const int*)d_in[1];
    const float* W1 = (const float*)d_in[3];
    const float* b1 = (const float*)d_in[4];
    const float* W2 = (const float*)d_in[5];
    const float* b2 = (const float*)d_in[6];
    const float* W3 = (const float*)d_in[7];
    const float* b3 = (const float*)d_in[8];
    const float* W4 = (const float*)d_in[9];
    const float* b4 = (const float*)d_in[10];
    float* out = (float*)d_out;

    float *pA, *pB, *pT;
    __nv_bfloat16 *pAhi, *pAlo, *pBhi, *pBlo;
    cudaGetSymbolAddress((void**)&pA,   g_bufA);
    cudaGetSymbolAddress((void**)&pB,   g_bufB);
    cudaGetSymbolAddress((void**)&pT,   g_t);
    cudaGetSymbolAddress((void**)&pAhi, g_Ahi);
    cudaGetSymbolAddress((void**)&pAlo, g_Alo);
    cudaGetSymbolAddress((void**)&pBhi, g_Bhi);
    cudaGetSymbolAddress((void**)&pBlo, g_Blo);

    // graph preprocessing
    init_deg_kernel<<<(NN + 255) / 256, 256>>>();
    count_deg_kernel<<<(EE + 255) / 256, 256>>>(ei);
    scan_kernel<<<1, 1024>>>();
    fill_csr_kernel<<<(NNZ + 255) / 256, 256>>>(ei);

    dim3 gemm_grid(HH / 64, (NN + 127) / 128);     // (8, 79)
    const int gemm_smem = 2 * STG;                 // 48 KB (fits default limit)
    int agg_blocks = (NN * 32 + 255) / 256;

    dim3 cvA1((KP1 + 255) / 256, NN);
    dim3 cvB1((KP1 + 255) / 256, HH);
    dim3 cvB2((HH + 255) / 256, HH);

    // layer 1
    convA_kernel<<<cvA1, 256>>>(x, FIN, KP1);
    convB_kernel<<<cvB1, 256>>>(W1, FIN, KP1);
    mma_gemm_kernel<<<gemm_grid, 256, gemm_smem>>>(pAhi, pAlo, pBhi, pBlo, pA, NN, KP1);
    aggregate512_kernel<<<agg_blocks, 256>>>(pA, pB, b1, 1, 1);   // -> hi/lo pitch 512
    // layer 2
    convB_kernel<<<cvB2, 256>>>(W2, HH, HH);
    mma_gemm_kernel<<<gemm_grid, 256, gemm_smem>>>(pAhi, pAlo, pBhi, pBlo, pA, NN, HH);
    aggregate512_kernel<<<agg_blocks, 256>>>(pA, pB, b2, 1, 1);   // -> hi/lo
    // layer 3
    convB_kernel<<<cvB2, 256>>>(W3, HH, HH);
    mma_gemm_kernel<<<gemm_grid, 256, gemm_smem>>>(pAhi, pAlo, pBhi, pBlo, pA, NN, HH);
    aggregate512_kernel<<<agg_blocks, 256>>>(pA, pB, b3, 1, 0);   // -> fp32 bufB
    // layer 4 + log_softmax
    gemm_small_kernel<<<agg_blocks, 256>>>(pB, W4, pT);
    finalize_kernel<<<(NN + 255) / 256, 256>>>(pT, b4, out);
}

// round 10
// speedup vs baseline: 3.3589x; 1.2060x over previous
#include <cuda_runtime.h>
#include <cuda_fp16.h>
#include <math.h>
#include <stdint.h>

#define NN   10000
#define EE   160000
#define FIN  2208
#define KP1  2240          // FIN padded to multiple of 32
#define HH   512
#define CC   2
#define NNZ  (EE + NN)

// ---------------- scratch (static device globals; no allocation) ----------------
__device__ float g_bufA[NN * HH];            // GEMM output
__device__ float g_bufB[NN * HH];            // aggregation fp32 output (layer 3)
__device__ float g_t[NN * CC];
__device__ int   g_degi[NN];
__device__ float g_dinv[NN];
__device__ int   g_rowptr[NN + 1];
__device__ int   g_cursor[NN];
__device__ int   g_colsrc[NNZ];
__device__ float g_w[NNZ];
__device__ __align__(16) __half g_Ah[NN * KP1];   // A in fp16 (single term)
__device__ __align__(16) __half g_Bh[HH * KP1];   // W^T hi fp16, [N][Kpad] K-major
__device__ __align__(16) __half g_Bl[HH * KP1];   // W^T residual fp16

// ---------------- PTX helpers (sm_80-baseline, compile at compute_103) ----------
__device__ __forceinline__ uint32_t smem_u32(const void* p) {
    uint32_t a;
    asm("{ .reg .u64 t; cvta.to.shared.u64 t, %1; cvt.u32.u64 %0, t; }" : "=r"(a) : "l"(p));
    return a;
}
__device__ __forceinline__ void cpa16(uint32_t s, const void* g, int sz) {
    asm volatile("cp.async.cg.shared.global [%0], [%1], 16, %2;"
                 :: "r"(s), "l"(g), "r"(sz) : "memory");
}
__device__ __forceinline__ void cpa_commit() {
    asm volatile("cp.async.commit_group;" ::: "memory");
}
template <int N> __device__ __forceinline__ void cpa_wait() {
    asm volatile("cp.async.wait_group %0;" :: "n"(N) : "memory");
}
__device__ __forceinline__ void ldsm4(uint32_t& r0, uint32_t& r1, uint32_t& r2, uint32_t& r3,
                                      uint32_t addr) {
    asm volatile("ldmatrix.sync.aligned.m8n8.x4.shared.b16 {%0,%1,%2,%3}, [%4];"
                 : "=r"(r0), "=r"(r1), "=r"(r2), "=r"(r3) : "r"(addr));
}
__device__ __forceinline__ void mma16816(float* d, const uint32_t* a, const uint32_t* b) {
    asm volatile(
        "mma.sync.aligned.m16n8k16.row.col.f32.f16.f16.f32 "
        "{%0,%1,%2,%3}, {%4,%5,%6,%7}, {%8,%9}, {%0,%1,%2,%3};"
        : "+f"(d[0]), "+f"(d[1]), "+f"(d[2]), "+f"(d[3])
        : "r"(a[0]), "r"(a[1]), "r"(a[2]), "r"(a[3]), "r"(b[0]), "r"(b[1]));
}

// ---------------- graph preprocessing ----------------
__global__ void init_deg_kernel() {
    int i = blockIdx.x * blockDim.x + threadIdx.x;
    if (i < NN) g_degi[i] = 1;
}
__global__ void count_deg_kernel(const int* __restrict__ ei) {
    int e = blockIdx.x * blockDim.x + threadIdx.x;
    if (e < EE) atomicAdd(&g_degi[ei[EE + e]], 1);
}
__global__ void scan_kernel() {
    __shared__ int sh[1024];
    __shared__ int carry_sh;
    int tid = threadIdx.x;
    if (tid == 0) carry_sh = 0;
    __syncthreads();
    for (int base = 0; base < NN; base += 1024) {
        int i = base + tid;
        int v = (i < NN) ? g_degi[i] : 0;
        sh[tid] = v;
        __syncthreads();
        for (int off = 1; off < 1024; off <<= 1) {
            int t = (tid >= off) ? sh[tid - off] : 0;
            __syncthreads();
            sh[tid] += t;
            __syncthreads();
        }
        int excl = sh[tid] - v;
        int c = carry_sh;
        if (i < NN) {
            g_rowptr[i] = c + excl;
            g_cursor[i] = c + excl;
            g_dinv[i]   = rsqrtf((float)v);
        }
        __syncthreads();
        if (tid == 0) carry_sh = c + sh[1023];
        __syncthreads();
    }
    if (tid == 0) g_rowptr[NN] = carry_sh;
}
__global__ void fill_csr_kernel(const int* __restrict__ ei) {
    int e = blockIdx.x * blockDim.x + threadIdx.x;
    if (e < EE) {
        int s = ei[e], d = ei[EE + e];
        int slot = atomicAdd(&g_cursor[d], 1);
        g_colsrc[slot] = s;
        g_w[slot] = g_dinv[s] * g_dinv[d];
    } else if (e < EE + NN) {
        int i = e - EE;
        int slot = atomicAdd(&g_cursor[i], 1);
        g_colsrc[slot] = i;
        g_w[slot] = g_dinv[i] * g_dinv[i];
    }
}

// ---------------- conversion ----------------
// A: fp32 [M,Kin] -> fp16 [M,Kpad] (zero-padded)
__global__ void convA_kernel(const float* __restrict__ src, int Kin, int Kpad) {
    int k = blockIdx.x * blockDim.x + threadIdx.x;
    int m = blockIdx.y;
    if (k >= Kpad) return;
    float v = (k < Kin) ? src[(size_t)m * Kin + k] : 0.f;
    g_Ah[(size_t)m * Kpad + k] = __float2half(v);
}
// W: fp32 [Kin, 512] -> transposed hi/lo fp16 [512][Kpad]
__global__ void convB_kernel(const float* __restrict__ W, int Kin, int Kpad) {
    int k = blockIdx.x * blockDim.x + threadIdx.x;
    int n = blockIdx.y;
    if (k >= Kpad) return;
    float v = (k < Kin) ? W[(size_t)k * HH + n] : 0.f;
    __half h = __float2half(v);
    g_Bh[(size_t)n * Kpad + k] = h;
    g_Bl[(size_t)n * Kpad + k] = __float2half(v - __half2float(h));
}

// ---------------- MMA GEMM: C[M,512] = A @ B^T (2-term fp16 split, fp32 acc) -----
// BM=128, BN=64, BK=32; 256 threads = 8 warps (4Mx2N), warp tile 32x32.
// per stage: A 8K | Bh 4K | Bl 4K = 16K; 3-stage pipeline = 48K.
#define STG 16384
#define OFF_BH 8192
#define OFF_BL 12288
// swizzled byte offset for (row, 16B-seg) in a 64B-pitch tile
#define SWZ(r, s) (((r) << 6) + ((((s) ^ (((r) >> 1) & 3))) << 4))

__device__ __forceinline__ void issue_chunk(
    uint32_t sb, int stage, int k0, int tid, int rowBase, int colBase, int M, int Kpad,
    const __half* Ah, const __half* Bh, const __half* Bl)
{
    uint32_t st = sb + stage * STG;
#pragma unroll
    for (int s = 0; s < 2; s++) {                 // A: 512 segs, 2/thread
        int idx = tid + s * 256;
        int r = idx >> 2, kseg = idx & 3;
        int grow = rowBase + r;
        int valid = (grow < M);
        size_t goff = (size_t)(valid ? grow : 0) * Kpad + k0 + kseg * 8;
        cpa16(st + SWZ(r, kseg), Ah + goff, valid ? 16 : 0);
    }
    {                                             // B: 256 segs, 1/thread (hi+lo)
        int r = tid >> 2, kseg = tid & 3;
        size_t goff = (size_t)(colBase + r) * Kpad + k0 + kseg * 8;
        uint32_t soff = SWZ(r, kseg);
        cpa16(st + OFF_BH + soff, Bh + goff, 16);
        cpa16(st + OFF_BL + soff, Bl + goff, 16);
    }
}

__global__ __launch_bounds__(256) void mma_gemm_kernel(
    const __half* __restrict__ Ah, const __half* __restrict__ Bh,
    const __half* __restrict__ Bl, float* __restrict__ C, int M, int Kpad)
{
    extern __shared__ char smem[];
    uint32_t sb = smem_u32(smem);
    int tid = threadIdx.x, lane = tid & 31, wid = tid >> 5;
    int wm = wid >> 1, wn = wid & 1;
    int rowBase = blockIdx.y * 128, colBase = blockIdx.x * 64;
    int NC = Kpad >> 5;

    float d[2][4][4];
#pragma unroll
    for (int i = 0; i < 2; i++)
#pragma unroll
        for (int j = 0; j < 4; j++)
#pragma unroll
            for (int k = 0; k < 4; k++) d[i][j][k] = 0.f;

    issue_chunk(sb, 0, 0, tid, rowBase, colBase, M, Kpad, Ah, Bh, Bl);
    cpa_commit();
    issue_chunk(sb, 1, 32, tid, rowBase, colBase, M, Kpad, Ah, Bh, Bl);
    cpa_commit();

    // per-lane ldmatrix address components (row/seg within tile)
    int a_r = (lane & 7) + (((lane >> 3) & 1) << 3);   // + mt*16 + wm*32
    int a_s = lane >> 4;                               // + ks*2
    int b_r = (lane & 7) + ((lane >> 4) << 3);         // + half*16 + wn*32
    int b_s = (lane >> 3) & 1;                         // + ks*2

    for (int i = 0; i < NC; i++) {
        if (i + 2 < NC)
            issue_chunk(sb, (i + 2) % 3, (i + 2) << 5, tid, rowBase, colBase, M, Kpad,
                        Ah, Bh, Bl);
        cpa_commit();                 // always commit: constant group accounting
        cpa_wait<2>();                // stage i complete
        __syncthreads();
        uint32_t st = sb + (i % 3) * STG;
#pragma unroll
        for (int ks = 0; ks < 2; ks++) {
            uint32_t ah[2][4], bh[4][2], bl[4][2];
#pragma unroll
            for (int mt = 0; mt < 2; mt++) {
                int row = wm * 32 + mt * 16 + a_r;
                uint32_t off = SWZ(row, ks * 2 + a_s);
                ldsm4(ah[mt][0], ah[mt][1], ah[mt][2], ah[mt][3], st + off);
            }
#pragma unroll
            for (int h = 0; h < 2; h++) {
                int n = wn * 32 + h * 16 + b_r;
                uint32_t off = SWZ(n, ks * 2 + b_s);
                uint32_t r0, r1, r2, r3;
                ldsm4(r0, r1, r2, r3, st + OFF_BH + off);
                bh[h * 2][0] = r0; bh[h * 2][1] = r1;
                bh[h * 2 + 1][0] = r2; bh[h * 2 + 1][1] = r3;
                ldsm4(r0, r1, r2, r3, st + OFF_BL + off);
                bl[h * 2][0] = r0; bl[h * 2][1] = r1;
                bl[h * 2 + 1][0] = r2; bl[h * 2 + 1][1] = r3;
            }
#pragma unroll
            for (int mt = 0; mt < 2; mt++)
#pragma unroll
                for (int nt = 0; nt < 4; nt++) {
                    mma16816(d[mt][nt], ah[mt], bh[nt]);
                    mma16816(d[mt][nt], ah[mt], bl[nt]);
                }
        }
        __syncthreads();
    }

    // epilogue
#pragma unroll
    for (int mt = 0; mt < 2; mt++)
#pragma unroll
        for (int nt = 0; nt < 4; nt++) {
            int rg = rowBase + wm * 32 + mt * 16 + (lane >> 2);
            int cg = colBase + wn * 32 + nt * 8 + (lane & 3) * 2;
            if (rg < M)
                *(float2*)&C[(size_t)rg * HH + cg] = make_float2(d[mt][nt][0], d[mt][nt][1]);
            if (rg + 8 < M)
                *(float2*)&C[(size_t)(rg + 8) * HH + cg] = make_float2(d[mt][nt][2], d[mt][nt][3]);
        }
}

// ---------------- aggregation (+bias, +relu), fused fp16 output ------------------
// mode 0: write fp32 to outf; mode 1: write fp16 (pitch 512) to g_Ah
__global__ __launch_bounds__(256) void aggregate512_kernel(
    const float* __restrict__ in, float* __restrict__ outf,
    const float* __restrict__ bias, int do_relu, int mode)
{
    int gw = (blockIdx.x * blockDim.x + threadIdx.x) >> 5;
    int lane = threadIdx.x & 31;
    if (gw >= NN) return;
    int beg = g_rowptr[gw], end = g_rowptr[gw + 1];

    float4 acc[4];
#pragma unroll
    for (int j = 0; j < 4; j++) acc[j] = make_float4(0.f, 0.f, 0.f, 0.f);

    for (int e = beg; e < end; e++) {
        int c = g_colsrc[e];
        float w = g_w[e];
        const float4* row = (const float4*)(in + (size_t)c * HH);
#pragma unroll
        for (int j = 0; j < 4; j++) {
            float4 v = row[j * 32 + lane];
            acc[j].x += w * v.x; acc[j].y += w * v.y;
            acc[j].z += w * v.z; acc[j].w += w * v.w;
        }
    }
#pragma unroll
    for (int j = 0; j < 4; j++) {
        int f = (j * 32 + lane) * 4;
        float4 bv = *(const float4*)&bias[f];
        float4 r;
        r.x = acc[j].x + bv.x; r.y = acc[j].y + bv.y;
        r.z = acc[j].z + bv.z; r.w = acc[j].w + bv.w;
        if (do_relu) {
            r.x = fmaxf(r.x, 0.f); r.y = fmaxf(r.y, 0.f);
            r.z = fmaxf(r.z, 0.f); r.w = fmaxf(r.w, 0.f);
        }
        if (mode == 0) {
            *(float4*)&outf[(size_t)gw * HH + f] = r;
        } else {
            __half2 h01 = __floats2half2_rn(r.x, r.y);
            __half2 h23 = __floats2half2_rn(r.z, r.w);
            *(__half2*)&g_Ah[(size_t)gw * HH + f]     = h01;
            *(__half2*)&g_Ah[(size_t)gw * HH + f + 2] = h23;
        }
    }
}

// ---------------- layer 4 + finalize ----------------
__global__ __launch_bounds__(256) void gemm_small_kernel(
    const float* __restrict__ h, const float* __restrict__ W4, float* __restrict__ t)
{
    __shared__ float w[HH * CC];
    int tid = threadIdx.x;
    for (int i = tid; i < HH * CC; i += blockDim.x) w[i] = W4[i];
    __syncthreads();
    int gw = (blockIdx.x * blockDim.x + tid) >> 5;
    int lane = tid & 31;
    if (gw >= NN) return;
    float a0 = 0.f, a1 = 0.f;
    const float* hr = h + (size_t)gw * HH;
    for (int k = lane; k < HH; k += 32) {
        float hv = hr[k];
        a0 += hv * w[2 * k + 0];
        a1 += hv * w[2 * k + 1];
    }
#pragma unroll
    for (int off = 16; off > 0; off >>= 1) {
        a0 += __shfl_down_sync(0xFFFFFFFFu, a0, off);
        a1 += __shfl_down_sync(0xFFFFFFFFu, a1, off);
    }
    if (lane == 0) { t[gw * 2 + 0] = a0; t[gw * 2 + 1] = a1; }
}

__global__ void finalize_kernel(const float* __restrict__ t,
                                const float* __restrict__ b4,
                                float* __restrict__ out)
{
    int i = blockIdx.x * blockDim.x + threadIdx.x;
    if (i >= NN) return;
    float z0 = 0.f, z1 = 0.f;
    int beg = g_rowptr[i], end = g_rowptr[i + 1];
    for (int e = beg; e < end; e++) {
        int c = g_colsrc[e];
        float w = g_w[e];
        z0 += w * t[2 * c + 0];
        z1 += w * t[2 * c + 1];
    }
    z0 += b4[0]; z1 += b4[1];
    float m = fmaxf(z0, z1);
    float lse = m + logf(expf(z0 - m) + expf(z1 - m));
    out[2 * i + 0] = z0 - lse;
    out[2 * i + 1] = z1 - lse;
}

// ---------------- launch ----------------
extern "C" void kernel_launch(void* const* d_in, const int* in_sizes, int n_in,
                              void* d_out, int out_size)
{
    const float* x  = (const float*)d_in[0];
    const int*   ei = (const int*)d_in[1];
    const float* W1 = (const float*)d_in[3];
    const float* b1 = (const float*)d_in[4];
    const float* W2 = (const float*)d_in[5];
    const float* b2 = (const float*)d_in[6];
    const float* W3 = (const float*)d_in[7];
    const float* b3 = (const float*)d_in[8];
    const float* W4 = (const float*)d_in[9];
    const float* b4 = (const float*)d_in[10];
    float* out = (float*)d_out;

    float *pA, *pB, *pT;
    __half *pAh, *pBh, *pBl;
    cudaGetSymbolAddress((void**)&pA,  g_bufA);
    cudaGetSymbolAddress((void**)&pB,  g_bufB);
    cudaGetSymbolAddress((void**)&pT,  g_t);
    cudaGetSymbolAddress((void**)&pAh, g_Ah);
    cudaGetSymbolAddress((void**)&pBh, g_Bh);
    cudaGetSymbolAddress((void**)&pBl, g_Bl);

    // graph preprocessing
    init_deg_kernel<<<(NN + 255) / 256, 256>>>();
    count_deg_kernel<<<(EE + 255) / 256, 256>>>(ei);
    scan_kernel<<<1, 1024>>>();
    fill_csr_kernel<<<(NNZ + 255) / 256, 256>>>(ei);

    dim3 gemm_grid(HH / 64, (NN + 127) / 128);     // (8, 79)
    const int gemm_smem = 3 * STG;                 // 48 KB (fits default limit)
    int agg_blocks = (NN * 32 + 255) / 256;

    dim3 cvA1((KP1 + 255) / 256, NN);
    dim3 cvB1((KP1 + 255) / 256, HH);
    dim3 cvB2((HH + 255) / 256, HH);

    // layer 1
    convA_kernel<<<cvA1, 256>>>(x, FIN, KP1);
    convB_kernel<<<cvB1, 256>>>(W1, FIN, KP1);
    mma_gemm_kernel<<<gemm_grid, 256, gemm_smem>>>(pAh, pBh, pBl, pA, NN, KP1);
    aggregate512_kernel<<<agg_blocks, 256>>>(pA, pB, b1, 1, 1);   // -> fp16 pitch 512
    // layer 2
    convB_kernel<<<cvB2, 256>>>(W2, HH, HH);
    mma_gemm_kernel<<<gemm_grid, 256, gemm_smem>>>(pAh, pBh, pBl, pA, NN, HH);
    aggregate512_kernel<<<agg_blocks, 256>>>(pA, pB, b2, 1, 1);   // -> fp16
    // layer 3
    convB_kernel<<<cvB2, 256>>>(W3, HH, HH);
    mma_gemm_kernel<<<gemm_grid, 256, gemm_smem>>>(pAh, pBh, pBl, pA, NN, HH);
    aggregate512_kernel<<<agg_blocks, 256>>>(pA, pB, b3, 1, 0);   // -> fp32 bufB
    // layer 4 + log_softmax
    gemm_small_kernel<<<agg_blocks, 256>>>(pB, W4, pT);
    finalize_kernel<<<(NN + 255) / 256, 256>>>(pT, b4, out);
}

// round 11
// speedup vs baseline: 4.3553x; 1.2966x over previous
#include <cuda_runtime.h>
#include <cuda_fp16.h>
#include <math.h>
#include <stdint.h>

#define NN   10000
#define EE   160000
#define FIN  2208
#define KP1  2240          // FIN padded to multiple of 32
#define HH   512
#define CC   2
#define NNZ  (EE + NN)

// ---------------- scratch (static device globals; no allocation) ----------------
__device__ float g_bufB[NN * HH];                 // agg3 fp32 output
__device__ float g_t[NN * CC];
__device__ int   g_degi[NN];
__device__ float g_dinv[NN];
__device__ int   g_rowptr[NN + 1];
__device__ int   g_cursor[NN];
__device__ int   g_colsrc[NNZ];
__device__ float g_w[NNZ];
__device__ __align__(16) __half g_Ah[NN * KP1];   // GEMM A operand (fp16)
__device__ __align__(16) __half g_H[NN * HH];     // GEMM fp16 output
__device__ __align__(16) __half g_Bh[HH * KP1];   // W^T fp16, [N][Kpad] K-major

// ---------------- PTX helpers (sm_80-baseline, compile at compute_103) ----------
__device__ __forceinline__ uint32_t smem_u32(const void* p) {
    uint32_t a;
    asm("{ .reg .u64 t; cvta.to.shared.u64 t, %1; cvt.u32.u64 %0, t; }" : "=r"(a) : "l"(p));
    return a;
}
__device__ __forceinline__ void cpa16(uint32_t s, const void* g, int sz) {
    asm volatile("cp.async.cg.shared.global [%0], [%1], 16, %2;"
                 :: "r"(s), "l"(g), "r"(sz) : "memory");
}
__device__ __forceinline__ void cpa_commit() {
    asm volatile("cp.async.commit_group;" ::: "memory");
}
template <int N> __device__ __forceinline__ void cpa_wait() {
    asm volatile("cp.async.wait_group %0;" :: "n"(N) : "memory");
}
__device__ __forceinline__ void ldsm4(uint32_t& r0, uint32_t& r1, uint32_t& r2, uint32_t& r3,
                                      uint32_t addr) {
    asm volatile("ldmatrix.sync.aligned.m8n8.x4.shared.b16 {%0,%1,%2,%3}, [%4];"
                 : "=r"(r0), "=r"(r1), "=r"(r2), "=r"(r3) : "r"(addr));
}
__device__ __forceinline__ void mma16816(float* d, const uint32_t* a, const uint32_t* b) {
    asm volatile(
        "mma.sync.aligned.m16n8k16.row.col.f32.f16.f16.f32 "
        "{%0,%1,%2,%3}, {%4,%5,%6,%7}, {%8,%9}, {%0,%1,%2,%3};"
        : "+f"(d[0]), "+f"(d[1]), "+f"(d[2]), "+f"(d[3])
        : "r"(a[0]), "r"(a[1]), "r"(a[2]), "r"(a[3]), "r"(b[0]), "r"(b[1]));
}

// ---------------- graph preprocessing ----------------
__global__ void init_deg_kernel() {
    int i = blockIdx.x * blockDim.x + threadIdx.x;
    if (i < NN) g_degi[i] = 1;
}
__global__ void count_deg_kernel(const int* __restrict__ ei) {
    int e = blockIdx.x * blockDim.x + threadIdx.x;
    if (e < EE) atomicAdd(&g_degi[ei[EE + e]], 1);
}
__global__ void scan_kernel() {
    __shared__ int sh[1024];
    __shared__ int carry_sh;
    int tid = threadIdx.x;
    if (tid == 0) carry_sh = 0;
    __syncthreads();
    for (int base = 0; base < NN; base += 1024) {
        int i = base + tid;
        int v = (i < NN) ? g_degi[i] : 0;
        sh[tid] = v;
        __syncthreads();
        for (int off = 1; off < 1024; off <<= 1) {
            int t = (tid >= off) ? sh[tid - off] : 0;
            __syncthreads();
            sh[tid] += t;
            __syncthreads();
        }
        int excl = sh[tid] - v;
        int c = carry_sh;
        if (i < NN) {
            g_rowptr[i] = c + excl;
            g_cursor[i] = c + excl;
            g_dinv[i]   = rsqrtf((float)v);
        }
        __syncthreads();
        if (tid == 0) carry_sh = c + sh[1023];
        __syncthreads();
    }
    if (tid == 0) g_rowptr[NN] = carry_sh;
}
__global__ void fill_csr_kernel(const int* __restrict__ ei) {
    int e = blockIdx.x * blockDim.x + threadIdx.x;
    if (e < EE) {
        int s = ei[e], d = ei[EE + e];
        int slot = atomicAdd(&g_cursor[d], 1);
        g_colsrc[slot] = s;
        g_w[slot] = g_dinv[s] * g_dinv[d];
    } else if (e < EE + NN) {
        int i = e - EE;
        int slot = atomicAdd(&g_cursor[i], 1);
        g_colsrc[slot] = i;
        g_w[slot] = g_dinv[i] * g_dinv[i];
    }
}

// ---------------- conversion ----------------
// A: fp32 [M,Kin] -> fp16 [M,Kpad] (zero-padded)
__global__ void convA_kernel(const float* __restrict__ src, int Kin, int Kpad) {
    int k = blockIdx.x * blockDim.x + threadIdx.x;
    int m = blockIdx.y;
    if (k >= Kpad) return;
    float v = (k < Kin) ? src[(size_t)m * Kin + k] : 0.f;
    g_Ah[(size_t)m * Kpad + k] = __float2half(v);
}
// W: fp32 [Kin, 512] -> transposed fp16 [512][Kpad]
__global__ void convB_kernel(const float* __restrict__ W, int Kin, int Kpad) {
    int k = blockIdx.x * blockDim.x + threadIdx.x;
    int n = blockIdx.y;
    if (k >= Kpad) return;
    float v = (k < Kin) ? W[(size_t)k * HH + n] : 0.f;
    g_Bh[(size_t)n * Kpad + k] = __float2half(v);
}

// ---------------- MMA GEMM: H[M,512] = A @ B^T (fp16 in, fp32 acc, fp16 out) -----
// BM=128, BN=64, BK=32; 256 threads = 8 warps (4Mx2N), warp tile 32x32.
// per stage: A 8K | B 4K = 12K; 4-stage pipeline = 48K.
#define STG 12288
#define OFF_B 8192
// swizzled byte offset for (row, 16B-seg) in a 64B-pitch tile
#define SWZ(r, s) (((r) << 6) + ((((s) ^ (((r) >> 1) & 3))) << 4))

__device__ __forceinline__ void issue_chunk(
    uint32_t sb, int stage, int k0, int tid, int rowBase, int colBase, int M, int Kpad,
    const __half* Ah, const __half* Bh)
{
    uint32_t st = sb + stage * STG;
#pragma unroll
    for (int s = 0; s < 2; s++) {                 // A: 512 segs, 2/thread
        int idx = tid + s * 256;
        int r = idx >> 2, kseg = idx & 3;
        int grow = rowBase + r;
        int valid = (grow < M);
        size_t goff = (size_t)(valid ? grow : 0) * Kpad + k0 + kseg * 8;
        cpa16(st + SWZ(r, kseg), Ah + goff, valid ? 16 : 0);
    }
    {                                             // B: 256 segs, 1/thread
        int r = tid >> 2, kseg = tid & 3;
        size_t goff = (size_t)(colBase + r) * Kpad + k0 + kseg * 8;
        cpa16(st + OFF_B + SWZ(r, kseg), Bh + goff, 16);
    }
}

__global__ __launch_bounds__(256) void mma_gemm_kernel(
    const __half* __restrict__ Ah, const __half* __restrict__ Bh,
    __half* __restrict__ H, int M, int Kpad)
{
    extern __shared__ char smem[];
    uint32_t sb = smem_u32(smem);
    int tid = threadIdx.x, lane = tid & 31, wid = tid >> 5;
    int wm = wid >> 1, wn = wid & 1;
    int rowBase = blockIdx.y * 128, colBase = blockIdx.x * 64;
    int NC = Kpad >> 5;

    float d[2][4][4];
#pragma unroll
    for (int i = 0; i < 2; i++)
#pragma unroll
        for (int j = 0; j < 4; j++)
#pragma unroll
            for (int k = 0; k < 4; k++) d[i][j][k] = 0.f;

    issue_chunk(sb, 0, 0, tid, rowBase, colBase, M, Kpad, Ah, Bh);
    cpa_commit();
    issue_chunk(sb, 1, 32, tid, rowBase, colBase, M, Kpad, Ah, Bh);
    cpa_commit();
    issue_chunk(sb, 2, 64, tid, rowBase, colBase, M, Kpad, Ah, Bh);
    cpa_commit();

    // per-lane ldmatrix address components (row/seg within tile)
    int a_r = (lane & 7) + (((lane >> 3) & 1) << 3);   // + mt*16 + wm*32
    int a_s = lane >> 4;                               // + ks*2
    int b_r = (lane & 7) + ((lane >> 4) << 3);         // + half*16 + wn*32
    int b_s = (lane >> 3) & 1;                         // + ks*2

    for (int i = 0; i < NC; i++) {
        if (i + 3 < NC)
            issue_chunk(sb, (i + 3) & 3, (i + 3) << 5, tid, rowBase, colBase, M, Kpad,
                        Ah, Bh);
        cpa_commit();                 // constant group accounting
        cpa_wait<3>();                // stage i complete
        __syncthreads();
        uint32_t st = sb + (i & 3) * STG;
#pragma unroll
        for (int ks = 0; ks < 2; ks++) {
            uint32_t ah[2][4], bh[4][2];
#pragma unroll
            for (int mt = 0; mt < 2; mt++) {
                int row = wm * 32 + mt * 16 + a_r;
                uint32_t off = SWZ(row, ks * 2 + a_s);
                ldsm4(ah[mt][0], ah[mt][1], ah[mt][2], ah[mt][3], st + off);
            }
#pragma unroll
            for (int h = 0; h < 2; h++) {
                int n = wn * 32 + h * 16 + b_r;
                uint32_t off = SWZ(n, ks * 2 + b_s);
                uint32_t r0, r1, r2, r3;
                ldsm4(r0, r1, r2, r3, st + OFF_B + off);
                bh[h * 2][0] = r0; bh[h * 2][1] = r1;
                bh[h * 2 + 1][0] = r2; bh[h * 2 + 1][1] = r3;
            }
#pragma unroll
            for (int mt = 0; mt < 2; mt++)
#pragma unroll
                for (int nt = 0; nt < 4; nt++)
                    mma16816(d[mt][nt], ah[mt], bh[nt]);
        }
        __syncthreads();
    }

    // epilogue: fp16 output
#pragma unroll
    for (int mt = 0; mt < 2; mt++)
#pragma unroll
        for (int nt = 0; nt < 4; nt++) {
            int rg = rowBase + wm * 32 + mt * 16 + (lane >> 2);
            int cg = colBase + wn * 32 + nt * 8 + (lane & 3) * 2;
            if (rg < M)
                *(__half2*)&H[(size_t)rg * HH + cg] = __floats2half2_rn(d[mt][nt][0], d[mt][nt][1]);
            if (rg + 8 < M)
                *(__half2*)&H[(size_t)(rg + 8) * HH + cg] = __floats2half2_rn(d[mt][nt][2], d[mt][nt][3]);
        }
}

// ---------------- aggregation: fp16 gather, fp32 acc, +bias +relu ---------------
// mode 0: write fp32 to outf; mode 1: write fp16 (pitch 512) to g_Ah
__global__ __launch_bounds__(256) void aggregate512_kernel(
    const __half* __restrict__ in, float* __restrict__ outf,
    const float* __restrict__ bias, int do_relu, int mode)
{
    int gw = (blockIdx.x * blockDim.x + threadIdx.x) >> 5;
    int lane = threadIdx.x & 31;
    if (gw >= NN) return;
    int beg = g_rowptr[gw], end = g_rowptr[gw + 1];

    float acc[16];
#pragma unroll
    for (int j = 0; j < 16; j++) acc[j] = 0.f;

    for (int e = beg; e < end; e++) {
        int c = g_colsrc[e];
        float w = g_w[e];
        const uint4* row = (const uint4*)(in + (size_t)c * HH);
        uint4 v0 = row[lane];           // features lane*8 .. +7
        uint4 v1 = row[32 + lane];      // features 256+lane*8 .. +7
        const __half2* p0 = (const __half2*)&v0;
        const __half2* p1 = (const __half2*)&v1;
#pragma unroll
        for (int j = 0; j < 4; j++) {
            float2 f0 = __half22float2(p0[j]);
            float2 f1 = __half22float2(p1[j]);
            acc[2 * j + 0] += w * f0.x;
            acc[2 * j + 1] += w * f0.y;
            acc[8 + 2 * j + 0] += w * f1.x;
            acc[8 + 2 * j + 1] += w * f1.y;
        }
    }

    // add bias + relu, write out. half index h: 0 -> features lane*8, 1 -> 256+lane*8
#pragma unroll
    for (int h = 0; h < 2; h++) {
        int f = h * 256 + lane * 8;
        float r[8];
#pragma unroll
        for (int j = 0; j < 8; j++) {
            r[j] = acc[h * 8 + j] + bias[f + j];
            if (do_relu) r[j] = fmaxf(r[j], 0.f);
        }
        if (mode == 0) {
            *(float4*)&outf[(size_t)gw * HH + f]     = make_float4(r[0], r[1], r[2], r[3]);
            *(float4*)&outf[(size_t)gw * HH + f + 4] = make_float4(r[4], r[5], r[6], r[7]);
        } else {
            __half2 o[4];
#pragma unroll
            for (int j = 0; j < 4; j++) o[j] = __floats2half2_rn(r[2 * j], r[2 * j + 1]);
            *(uint4*)&g_Ah[(size_t)gw * HH + f] = *(uint4*)o;
        }
    }
}

// ---------------- layer 4 + finalize ----------------
__global__ __launch_bounds__(256) void gemm_small_kernel(
    const float* __restrict__ h, const float* __restrict__ W4, float* __restrict__ t)
{
    __shared__ float w[HH * CC];
    int tid = threadIdx.x;
    for (int i = tid; i < HH * CC; i += blockDim.x) w[i] = W4[i];
    __syncthreads();
    int gw = (blockIdx.x * blockDim.x + tid) >> 5;
    int lane = tid & 31;
    if (gw >= NN) return;
    float a0 = 0.f, a1 = 0.f;
    const float* hr = h + (size_t)gw * HH;
    for (int k = lane; k < HH; k += 32) {
        float hv = hr[k];
        a0 += hv * w[2 * k + 0];
        a1 += hv * w[2 * k + 1];
    }
#pragma unroll
    for (int off = 16; off > 0; off >>= 1) {
        a0 += __shfl_down_sync(0xFFFFFFFFu, a0, off);
        a1 += __shfl_down_sync(0xFFFFFFFFu, a1, off);
    }
    if (lane == 0) { t[gw * 2 + 0] = a0; t[gw * 2 + 1] = a1; }
}

__global__ void finalize_kernel(const float* __restrict__ t,
                                const float* __restrict__ b4,
                                float* __restrict__ out)
{
    int i = blockIdx.x * blockDim.x + threadIdx.x;
    if (i >= NN) return;
    float z0 = 0.f, z1 = 0.f;
    int beg = g_rowptr[i], end = g_rowptr[i + 1];
    for (int e = beg; e < end; e++) {
        int c = g_colsrc[e];
        float w = g_w[e];
        z0 += w * t[2 * c + 0];
        z1 += w * t[2 * c + 1];
    }
    z0 += b4[0]; z1 += b4[1];
    float m = fmaxf(z0, z1);
    float lse = m + logf(expf(z0 - m) + expf(z1 - m));
    out[2 * i + 0] = z0 - lse;
    out[2 * i + 1] = z1 - lse;
}

// ---------------- launch ----------------
extern "C" void kernel_launch(void* const* d_in, const int* in_sizes, int n_in,
                              void* d_out, int out_size)
{
    const float* x  = (const float*)d_in[0];
    const int*   ei = (const int*)d_in[1];
    const float* W1 = (const float*)d_in[3];
    const float* b1 = (const float*)d_in[4];
    const float* W2 = (const float*)d_in[5];
    const float* b2 = (const float*)d_in[6];
    const float* W3 = (const float*)d_in[7];
    const float* b3 = (const float*)d_in[8];
    const float* W4 = (const float*)d_in[9];
    const float* b4 = (const float*)d_in[10];
    float* out = (float*)d_out;

    float *pB, *pT;
    __half *pAh, *pBh, *pH;
    cudaGetSymbolAddress((void**)&pB,  g_bufB);
    cudaGetSymbolAddress((void**)&pT,  g_t);
    cudaGetSymbolAddress((void**)&pAh, g_Ah);
    cudaGetSymbolAddress((void**)&pBh, g_Bh);
    cudaGetSymbolAddress((void**)&pH,  g_H);

    // graph preprocessing
    init_deg_kernel<<<(NN + 255) / 256, 256>>>();
    count_deg_kernel<<<(EE + 255) / 256, 256>>>(ei);
    scan_kernel<<<1, 1024>>>();
    fill_csr_kernel<<<(NNZ + 255) / 256, 256>>>(ei);

    dim3 gemm_grid(HH / 64, (NN + 127) / 128);     // (8, 79)
    const int gemm_smem = 4 * STG;                 // 48 KB
    int agg_blocks = (NN * 32 + 255) / 256;

    dim3 cvA1((KP1 + 255) / 256, NN);
    dim3 cvB1((KP1 + 255) / 256, HH);
    dim3 cvB2((HH + 255) / 256, HH);

    // layer 1
    convA_kernel<<<cvA1, 256>>>(x, FIN, KP1);
    convB_kernel<<<cvB1, 256>>>(W1, FIN, KP1);
    mma_gemm_kernel<<<gemm_grid, 256, gemm_smem>>>(pAh, pBh, pH, NN, KP1);
    aggregate512_kernel<<<agg_blocks, 256>>>(pH, pB, b1, 1, 1);   // -> fp16 g_Ah
    // layer 2
    convB_kernel<<<cvB2, 256>>>(W2, HH, HH);
    mma_gemm_kernel<<<gemm_grid, 256, gemm_smem>>>(pAh, pBh, pH, NN, HH);
    aggregate512_kernel<<<agg_blocks, 256>>>(pH, pB, b2, 1, 1);   // -> fp16 g_Ah
    // layer 3
    convB_kernel<<<cvB2, 256>>>(W3, HH, HH);
    mma_gemm_kernel<<<gemm_grid, 256, gemm_smem>>>(pAh, pBh, pH, NN, HH);
    aggregate512_kernel<<<agg_blocks, 256>>>(pH, pB, b3, 1, 0);   // -> fp32 bufB
    // layer 4 + log_softmax
    gemm_small_kernel<<<agg_blocks, 256>>>(pB, W4, pT);
    finalize_kernel<<<(NN + 255) / 256, 256>>>(pT, b4, out);
}